// round 2
// baseline (speedup 1.0000x reference)
#include <cuda_runtime.h>

#define NN 64
#define CC 64
#define HH 128
#define WW 128
#define OH 126
#define OW 126
#define TILE_ROWS 34          // 32 output rows + 2 halo
#define TILE_STRIDE 132       // 128 cols padded (keeps 16B alignment, no bank pathologies)
#define SM_TILE (TILE_ROWS * TILE_STRIDE)

__device__ __forceinline__ void cp_async16(void* smem, const void* gmem) {
    unsigned saddr = (unsigned)__cvta_generic_to_shared(smem);
    asm volatile("cp.async.cg.shared.global [%0], [%1], 16;\n" :: "r"(saddr), "l"(gmem));
}
__device__ __forceinline__ void cp_commit() {
    asm volatile("cp.async.commit_group;\n" ::: "memory");
}
__device__ __forceinline__ void cp_wait0() {
    asm volatile("cp.async.wait_group 0;\n" ::: "memory");
}

__global__ __launch_bounds__(256, 2)
void imagewise_conv2d_kernel(const float* __restrict__ img,
                             const float* __restrict__ ker,
                             float* __restrict__ out) {
    __shared__ float wts[CC * 9];
    __shared__ __align__(16) float tile[2][SM_TILE];

    const int n     = blockIdx.x;      // sample
    const int yt    = blockIdx.y;      // row tile: 32 output rows each
    const int tid   = threadIdx.x;
    const int tx    = tid & 31;        // 32 col-groups
    const int ty    = tid >> 5;        // 8 row-groups
    const int x0    = tx * 4;          // output cols x0..x0+3
    const int y0    = ty * 4;          // output rows (in tile) y0..y0+3
    const int ybase = yt * 32;

    // Stage this sample's weights (576 floats) once.
    for (int e = tid; e < CC * 9; e += 256) wts[e] = ker[n * CC * 9 + e];

    const float* imgn = img + (size_t)n * CC * HH * WW;

    // Prologue: issue async loads for channel 0 into buffer 0.
    {
        const float* src = imgn;  // c = 0
        #pragma unroll
        for (int k = 0; k < 5; ++k) {
            int idx = tid + k * 256;               // 34 rows * 32 float4 = 1088
            if (idx < TILE_ROWS * 32) {
                int r  = idx >> 5;
                int c4 = (idx & 31) * 4;
                int rg = ybase + r; if (rg > HH - 1) rg = HH - 1;  // clamp (masked rows)
                cp_async16(&tile[0][r * TILE_STRIDE + c4], src + rg * WW + c4);
            }
        }
        cp_commit();
    }

    float acc[16];
    #pragma unroll
    for (int i = 0; i < 16; ++i) acc[i] = 0.0f;

    for (int c = 0; c < CC; ++c) {
        const int cur = c & 1;

        cp_wait0();        // this thread's copies for channel c landed
        __syncthreads();   // everyone's copies visible; prev compute (on buf cur^1) done

        // Overlap: issue channel c+1 loads into the other buffer while computing c.
        if (c + 1 < CC) {
            const float* src = imgn + (size_t)(c + 1) * HH * WW;
            #pragma unroll
            for (int k = 0; k < 5; ++k) {
                int idx = tid + k * 256;
                if (idx < TILE_ROWS * 32) {
                    int r  = idx >> 5;
                    int c4 = (idx & 31) * 4;
                    int rg = ybase + r; if (rg > HH - 1) rg = HH - 1;
                    cp_async16(&tile[cur ^ 1][r * TILE_STRIDE + c4], src + rg * WW + c4);
                }
            }
            cp_commit();
        }

        // ---- compute channel c on tile[cur] ----
        float w[9];
        #pragma unroll
        for (int i = 0; i < 9; ++i) w[i] = wts[c * 9 + i];

        const float* t = &tile[cur][0];
        #pragma unroll
        for (int j = 0; j < 6; ++j) {               // 6 input rows feed 4 output rows
            const float* row = t + (y0 + j) * TILE_STRIDE + x0;  // 16B aligned
            const float4 p = *(const float4*)(row);
            const float2 q = *(const float2*)(row + 4);
            const float v0 = p.x, v1 = p.y, v2 = p.z, v3 = p.w, v4 = q.x, v5 = q.y;
            #pragma unroll
            for (int kh = 0; kh < 3; ++kh) {
                const int ro = j - kh;               // compile-time after unroll
                if (ro >= 0 && ro < 4) {
                    const float w0 = w[kh * 3 + 0];
                    const float w1 = w[kh * 3 + 1];
                    const float w2 = w[kh * 3 + 2];
                    acc[ro * 4 + 0] = fmaf(v0, w0, acc[ro * 4 + 0]);
                    acc[ro * 4 + 0] = fmaf(v1, w1, acc[ro * 4 + 0]);
                    acc[ro * 4 + 0] = fmaf(v2, w2, acc[ro * 4 + 0]);
                    acc[ro * 4 + 1] = fmaf(v1, w0, acc[ro * 4 + 1]);
                    acc[ro * 4 + 1] = fmaf(v2, w1, acc[ro * 4 + 1]);
                    acc[ro * 4 + 1] = fmaf(v3, w2, acc[ro * 4 + 1]);
                    acc[ro * 4 + 2] = fmaf(v2, w0, acc[ro * 4 + 2]);
                    acc[ro * 4 + 2] = fmaf(v3, w1, acc[ro * 4 + 2]);
                    acc[ro * 4 + 2] = fmaf(v4, w2, acc[ro * 4 + 2]);
                    acc[ro * 4 + 3] = fmaf(v3, w0, acc[ro * 4 + 3]);
                    acc[ro * 4 + 3] = fmaf(v4, w1, acc[ro * 4 + 3]);
                    acc[ro * 4 + 3] = fmaf(v5, w2, acc[ro * 4 + 3]);
                }
            }
        }
    }

    // ---- store (mask the 126-col / 126-row edges) ----
    const int gy0 = ybase + y0;
    #pragma unroll
    for (int ry = 0; ry < 4; ++ry) {
        const int y = gy0 + ry;
        if (y < OH) {
            float* o = out + ((size_t)n * OH + y) * OW + x0;
            #pragma unroll
            for (int xc = 0; xc < 4; ++xc) {
                if (x0 + xc < OW) o[xc] = acc[ry * 4 + xc];
            }
        }
    }
}

extern "C" void kernel_launch(void* const* d_in, const int* in_sizes, int n_in,
                              void* d_out, int out_size) {
    const float* img = (const float*)d_in[0];   // [64,64,128,128] f32
    const float* ker = (const float*)d_in[1];   // [64,64,3,3]     f32
    float* out       = (float*)d_out;           // [64,1,126,126]  f32

    dim3 grid(NN, 4);   // 64 samples x 4 row-tiles (32 rows each)
    imagewise_conv2d_kernel<<<grid, 256>>>(img, ker, out);
}

// round 3
// speedup vs baseline: 1.0737x; 1.0737x over previous
#include <cuda_runtime.h>

#define NN 64
#define CC 64
#define HH 128
#define WW 128
#define OH 126
#define OW 126
#define OUT_ROWS_PER_TILE 16
#define N_TILES 8             // 8 * 16 = 128 rows covered (126 valid)
#define TILE_ROWS 18          // 16 output rows + 2 halo
#define TILE_STRIDE 132       // 128 cols padded to keep 16B alignment
#define SM_TILE (TILE_ROWS * TILE_STRIDE)
#define STAGES 3
#define CP_PER_STAGE (TILE_ROWS * 32)   // 576 float4 copies

__device__ __forceinline__ void cp_async16(void* smem, const void* gmem) {
    unsigned saddr = (unsigned)__cvta_generic_to_shared(smem);
    asm volatile("cp.async.cg.shared.global [%0], [%1], 16;\n" :: "r"(saddr), "l"(gmem));
}
__device__ __forceinline__ void cp_commit() {
    asm volatile("cp.async.commit_group;\n" ::: "memory");
}
__device__ __forceinline__ void cp_wait1() {
    asm volatile("cp.async.wait_group 1;\n" ::: "memory");
}
__device__ __forceinline__ void cp_wait0() {
    asm volatile("cp.async.wait_group 0;\n" ::: "memory");
}

__global__ __launch_bounds__(256, 4)
void imagewise_conv2d_kernel(const float* __restrict__ img,
                             const float* __restrict__ ker,
                             float* __restrict__ out) {
    __shared__ float wts[CC * 9];
    __shared__ __align__(16) float tile[STAGES][SM_TILE];

    const int n     = blockIdx.x;      // sample
    const int yt    = blockIdx.y;      // row tile: 16 output rows each
    const int tid   = threadIdx.x;
    const int tx    = tid & 31;        // 32 col-groups
    const int ty    = tid >> 5;        // 8 row-groups x 2 rows
    const int x0    = tx * 4;          // output cols x0..x0+3
    const int y0    = ty * 2;          // output rows (in tile) y0..y0+1
    const int ybase = yt * OUT_ROWS_PER_TILE;

    // Stage this sample's weights (576 floats) once.
    for (int e = tid; e < CC * 9; e += 256) wts[e] = ker[n * CC * 9 + e];

    const float* imgn = img + (size_t)n * CC * HH * WW;

    // Prologue: issue async loads for channels 0 and 1.
    #pragma unroll
    for (int pc = 0; pc < 2; ++pc) {
        const float* src = imgn + (size_t)pc * HH * WW;
        #pragma unroll
        for (int k = 0; k < 3; ++k) {
            int idx = tid + k * 256;               // 576 float4 per stage
            if (idx < CP_PER_STAGE) {
                int r  = idx >> 5;
                int c4 = (idx & 31) * 4;
                int rg = ybase + r; if (rg > HH - 1) rg = HH - 1;  // clamp halo
                cp_async16(&tile[pc][r * TILE_STRIDE + c4], src + rg * WW + c4);
            }
        }
        cp_commit();
    }

    float acc[8];
    #pragma unroll
    for (int i = 0; i < 8; ++i) acc[i] = 0.0f;

    for (int c = 0; c < CC; ++c) {
        const int cur = c % STAGES;

        // Wait for channel c's stage (allow one newer group to stay in flight).
        if (c + 1 < CC) cp_wait1(); else cp_wait0();
        __syncthreads();   // c's data visible to all; compute of c-1 (same stage as c+2) done

        // Issue channel c+2 into stage (c+2)%STAGES (== stage of c-1, now free).
        if (c + 2 < CC) {
            const int nxt = (c + 2) % STAGES;
            const float* src = imgn + (size_t)(c + 2) * HH * WW;
            #pragma unroll
            for (int k = 0; k < 3; ++k) {
                int idx = tid + k * 256;
                if (idx < CP_PER_STAGE) {
                    int r  = idx >> 5;
                    int c4 = (idx & 31) * 4;
                    int rg = ybase + r; if (rg > HH - 1) rg = HH - 1;
                    cp_async16(&tile[nxt][r * TILE_STRIDE + c4], src + rg * WW + c4);
                }
            }
            cp_commit();
        }

        // ---- compute channel c on tile[cur] ----
        float w[9];
        #pragma unroll
        for (int i = 0; i < 9; ++i) w[i] = wts[c * 9 + i];

        const float* t = &tile[cur][0];
        #pragma unroll
        for (int j = 0; j < 4; ++j) {               // 4 input rows feed 2 output rows
            const float* row = t + (y0 + j) * TILE_STRIDE + x0;  // 16B aligned
            const float4 p = *(const float4*)(row);
            const float2 q = *(const float2*)(row + 4);
            const float v0 = p.x, v1 = p.y, v2 = p.z, v3 = p.w, v4 = q.x, v5 = q.y;
            #pragma unroll
            for (int kh = 0; kh < 3; ++kh) {
                const int ro = j - kh;               // compile-time after unroll
                if (ro >= 0 && ro < 2) {
                    const float w0 = w[kh * 3 + 0];
                    const float w1 = w[kh * 3 + 1];
                    const float w2 = w[kh * 3 + 2];
                    acc[ro * 4 + 0] = fmaf(v0, w0, acc[ro * 4 + 0]);
                    acc[ro * 4 + 0] = fmaf(v1, w1, acc[ro * 4 + 0]);
                    acc[ro * 4 + 0] = fmaf(v2, w2, acc[ro * 4 + 0]);
                    acc[ro * 4 + 1] = fmaf(v1, w0, acc[ro * 4 + 1]);
                    acc[ro * 4 + 1] = fmaf(v2, w1, acc[ro * 4 + 1]);
                    acc[ro * 4 + 1] = fmaf(v3, w2, acc[ro * 4 + 1]);
                    acc[ro * 4 + 2] = fmaf(v2, w0, acc[ro * 4 + 2]);
                    acc[ro * 4 + 2] = fmaf(v3, w1, acc[ro * 4 + 2]);
                    acc[ro * 4 + 2] = fmaf(v4, w2, acc[ro * 4 + 2]);
                    acc[ro * 4 + 3] = fmaf(v3, w0, acc[ro * 4 + 3]);
                    acc[ro * 4 + 3] = fmaf(v4, w1, acc[ro * 4 + 3]);
                    acc[ro * 4 + 3] = fmaf(v5, w2, acc[ro * 4 + 3]);
                }
            }
        }
    }

    // ---- store (mask the 126-col / 126-row edges) ----
    const int gy0 = ybase + y0;
    #pragma unroll
    for (int ry = 0; ry < 2; ++ry) {
        const int y = gy0 + ry;
        if (y < OH) {
            float* o = out + ((size_t)n * OH + y) * OW + x0;
            #pragma unroll
            for (int xc = 0; xc < 4; ++xc) {
                if (x0 + xc < OW) o[xc] = acc[ry * 4 + xc];
            }
        }
    }
}

extern "C" void kernel_launch(void* const* d_in, const int* in_sizes, int n_in,
                              void* d_out, int out_size) {
    const float* img = (const float*)d_in[0];   // [64,64,128,128] f32
    const float* ker = (const float*)d_in[1];   // [64,64,3,3]     f32
    float* out       = (float*)d_out;           // [64,1,126,126]  f32

    dim3 grid(NN, N_TILES);   // 64 samples x 8 row-tiles (16 rows each)
    imagewise_conv2d_kernel<<<grid, 256>>>(img, ker, out);
}